// round 13
// baseline (speedup 1.0000x reference)
#include <cuda_runtime.h>
#include <math.h>

#define CONF_TH 0.25f
#define NMS_TH  0.35f
#define FULL    0xffffffffu

static constexpr int N_IMG = 64;
static constexpr int HW    = 1024;   // 32*32
static constexpr int NCH   = 85;
static constexpr int NCLS  = 80;
static constexpr int SLOTS = 32;

// static scratch (zero-initialized; flag/done invariants restored every run)
__device__ unsigned long long g_ckey[N_IMG * 2 * 512];   // compacted candidate keys
__device__ float4             g_cbox[N_IMG * 2 * 512];   // compacted candidate boxes
__device__ unsigned           g_ccnt[N_IMG * 2];         // candidate counts (overwritten)
__device__ unsigned           g_flag[N_IMG];             // exchange rendezvous
__device__ unsigned           g_done[N_IMG];             // cleanup ticket

// dynamic smem layout (bytes):
//  pval    float4[1024] @      0 (16384)
//  pidx    int4  [1024] @  16384 (16384)
//  skeyAll u64   [1024] @  32768 ( 8192)   merged candidate keys (mine + partner)
//  sboxAll float4[1024] @  40960 (16384)   merged candidate boxes
//  sstate  u32   [1024] @  57344 ( 4096)   fallback state
//  sslot   u64 [80*32]  @  61440 (20480)
//  scnt    u32   [80]   @  81920 (  320)
//  posmap  u16   [1024] @  82240 ( 2048)   pixel pos -> list index
//  scand   u32          @  84288 (    4)   my candidate count
//  spc     u32          @  84292 (    4)   partner candidate count
static constexpr int SMEM_BYTES = 84296;

__device__ __forceinline__ unsigned long long bitonic_shfl_step(
    unsigned long long key, int j, bool up, int t)
{
    unsigned long long p = __shfl_xor_sync(FULL, key, j);
    bool low     = ((t & j) == 0);
    bool takeMin = (low == up);
    bool swap    = takeMin ? (p < key) : (p > key);
    return swap ? p : key;
}

__global__ __launch_bounds__(1024, 1)
void fastestdet_kernel(const float* __restrict__ in, float* __restrict__ out)
{
    extern __shared__ unsigned char smem_raw[];
    float4*             pval    = (float4*)(smem_raw);
    int4*               pidx    = (int4*)  (smem_raw + 16384);
    unsigned long long* skeyAll = (unsigned long long*)(smem_raw + 32768);
    float4*             sboxAll = (float4*)(smem_raw + 40960);
    unsigned*           sstate  = (unsigned*)(smem_raw + 57344);
    unsigned long long* sslot   = (unsigned long long*)(smem_raw + 61440);
    unsigned*           scnt    = (unsigned*)(smem_raw + 81920);
    unsigned short*     posmap  = (unsigned short*)(smem_raw + 82240);
    unsigned*           scand   = (unsigned*)(smem_raw + 84288);
    unsigned*           spc     = (unsigned*)(smem_raw + 84292);

    const int n    = blockIdx.x >> 1;   // image
    const int half = blockIdx.x & 1;    // half-image [half*512, half*512+512)
    const int t    = threadIdx.x;
    const int lane = t & 31;
    const int wid  = t >> 5;
    const int g    = t & 127;    // pixel group (4 px) within half
    const int q    = t >> 7;     // class chunk (10 classes each)

    sstate[t] = 0u;
    if (t < NCLS) scnt[t] = 0u;
    if (t == 0) *scand = 0u;

    // ---------------- decode phase 1: partial argmax over 10 classes ----------------
    const float4* base = (const float4*)(in + (size_t)n * NCH * HW) + half * 128 + g;

    float4 bv = make_float4(-INFINITY, -INFINITY, -INFINITY, -INFINITY);
    int4   bj = make_int4(0, 0, 0, 0);
    const int c0 = q * 10;
    #pragma unroll
    for (int cc = 0; cc < 10; cc++) {
        int c = c0 + cc;
        float4 v = base[(5 + c) * 256];
        if (v.x > bv.x) { bv.x = v.x; bj.x = c; }
        if (v.y > bv.y) { bv.y = v.y; bj.y = c; }
        if (v.z > bv.z) { bv.z = v.z; bj.z = c; }
        if (v.w > bv.w) { bv.w = v.w; bj.w = c; }
    }
    pval[q * 128 + g] = bv;
    pidx[q * 128 + g] = bj;

    float4 pobj, r0, r1, r2, r3;
    if (q == 0) {
        pobj = base[0 * 256];
        r0   = base[1 * 256];
        r1   = base[2 * 256];
        r2   = base[3 * 256];
        r3   = base[4 * 256];
    }
    __syncthreads();

    // ---------------- decode phase 2: merge + box math (q==0 threads) ----------------
    if (q == 0) {
        float4 mv = pval[g];
        int4   mj = pidx[g];
        #pragma unroll
        for (int qq = 1; qq < 8; qq++) {
            float4 v = pval[qq * 128 + g];
            int4   j = pidx[qq * 128 + g];
            if (v.x > mv.x) { mv.x = v.x; mj.x = j.x; }   // strict >: lower class wins ties
            if (v.y > mv.y) { mv.y = v.y; mj.y = j.y; }
            if (v.z > mv.z) { mv.z = v.z; mj.z = j.z; }
            if (v.w > mv.w) { mv.w = v.w; mj.w = j.w; }
        }

        float sc[4]  = { pobj.x * mv.x, pobj.y * mv.y, pobj.z * mv.z, pobj.w * mv.w };
        float rr0[4] = { r0.x, r0.y, r0.z, r0.w };
        float rr1[4] = { r1.x, r1.y, r1.z, r1.w };
        float rr2[4] = { r2.x, r2.y, r2.z, r2.w };
        float rr3[4] = { r3.x, r3.y, r3.z, r3.w };
        int   cl[4]  = { mj.x, mj.y, mj.z, mj.w };

        float vals[24];
        #pragma unroll
        for (int l = 0; l < 4; l++) {
            int p = half * 512 + g * 4 + l;
            float gx = (float)(p & 31);
            float gy = (float)(p >> 5);
            float bcx = (tanhf(rr0[l]) + gx) * (1.0f / 32.0f);
            float bcy = (tanhf(rr1[l]) + gy) * (1.0f / 32.0f);
            float bw  = 1.0f / (1.0f + expf(-rr2[l]));
            float bh  = 1.0f / (1.0f + expf(-rr3[l]));
            float x1 = bcx - 0.5f * bw;
            float y1 = bcy - 0.5f * bh;
            float x2 = bcx + 0.5f * bw;
            float y2 = bcy + 0.5f * bh;

            vals[l * 6 + 0] = x1; vals[l * 6 + 1] = y1;
            vals[l * 6 + 2] = x2; vals[l * 6 + 3] = y2;
            vals[l * 6 + 4] = sc[l]; vals[l * 6 + 5] = (float)cl[l];

            if (sc[l] > CONF_TH) {
                unsigned u = __float_as_uint(sc[l]);
                u = (u & 0x80000000u) ? ~u : (u | 0x80000000u);   // ascending-sortable
                unsigned long long key =
                      ((unsigned long long)(unsigned)cl[l] << 42)
                    | ((unsigned long long)(~u) << 10)
                    | (unsigned)p;
                float4 b4 = make_float4(x1, y1, x2, y2);
                unsigned idx = atomicAdd(scand, 1u);      // < 512 guaranteed
                skeyAll[idx] = key;
                sboxAll[idx] = b4;
                posmap[p]    = (unsigned short)idx;
                g_ckey[((size_t)n * 2 + half) * 512 + idx] = key;
                g_cbox[((size_t)n * 2 + half) * 512 + idx] = b4;
            }
        }

        // boxes+score+cls out: 24 contiguous floats = 6 float4 stores
        float4* ob4 = (float4*)(out + ((size_t)n * HW + half * 512 + g * 4) * 6);
        #pragma unroll
        for (int qq = 0; qq < 6; qq++)
            ob4[qq] = make_float4(vals[qq * 4 + 0], vals[qq * 4 + 1],
                                  vals[qq * 4 + 2], vals[qq * 4 + 3]);

        // keep region default zeros for this half
        *(float4*)(out + (size_t)N_IMG * HW * 6 + (size_t)n * HW + half * 512 + g * 4) =
            make_float4(0.0f, 0.0f, 0.0f, 0.0f);
    }

    // ---------------- rendezvous: publish candidates, wait for partner ----------------
    __threadfence();
    __syncthreads();
    if (t == 0) {
        g_ccnt[n * 2 + half] = *scand;
        __threadfence();
        atomicAdd(&g_flag[n], 1u);
        volatile unsigned* vf = (volatile unsigned*)&g_flag[n];
        while (*vf < 2u) __nanosleep(20);
        __threadfence();                       // acquire
        *spc = g_ccnt[n * 2 + (half ^ 1)];
    }
    __syncthreads();

    // ---------------- pull partner candidates into smem ----------------
    const unsigned mycnt = *scand;
    const unsigned pc    = *spc;
    if (t < pc) {
        unsigned long long key = g_ckey[((size_t)n * 2 + (half ^ 1)) * 512 + t];
        float4             b4  = g_cbox[((size_t)n * 2 + (half ^ 1)) * 512 + t];
        unsigned idx = mycnt + t;
        skeyAll[idx] = key;
        sboxAll[idx] = b4;
        posmap[key & 0x3FFu] = (unsigned short)idx;
    }
    __syncthreads();

    // ---------------- build per-class slot table ----------------
    const int ncand = (int)(mycnt + pc);
    if (t < ncand) {
        unsigned long long key = skeyAll[t];
        int cls = (int)((key >> 42) & 0x7Fu);
        unsigned slot = atomicAdd(&scnt[cls], 1u);
        if (slot < SLOTS) sslot[cls * SLOTS + slot] = key;
    }
    __syncthreads();

    float* keep = out + (size_t)N_IMG * HW * 6 + (size_t)n * HW;

    // ---------------- warp-per-class greedy NMS (smem; both CTAs redundant) ----------------
    for (int c = wid; c < NCLS; c += 32) {
        int m = (int)scnt[c];
        if (m == 0) continue;

        if (m <= SLOTS) {
            unsigned long long kk = (lane < m) ? sslot[c * SLOTS + lane] : ~0ull;
            #pragma unroll
            for (int k = 2; k <= 32; k <<= 1) {
                #pragma unroll
                for (int j = k >> 1; j >= 1; j >>= 1)
                    kk = bitonic_shfl_step(kk, j, (lane & k) == 0, lane);
            }
            int pos = (int)(kk & 0x3FFu);
            int li  = (int)posmap[pos] & 1023;        // garbage-safe for lane>=m
            float4 b4 = sboxAll[li];
            float  ar = (b4.z - b4.x) * (b4.w - b4.y);

            unsigned removed = 0u, keepB = 0u;
            for (int i = 0; i < m; i++) {
                if ((removed >> i) & 1u) continue;    // uniform across warp
                keepB |= 1u << i;
                float wx1 = __shfl_sync(FULL, b4.x, i);
                float wy1 = __shfl_sync(FULL, b4.y, i);
                float wx2 = __shfl_sync(FULL, b4.z, i);
                float wy2 = __shfl_sync(FULL, b4.w, i);
                float wa  = __shfl_sync(FULL, ar,   i);
                float iw = fminf(b4.z, wx2) - fmaxf(b4.x, wx1);
                float ih = fminf(b4.w, wy2) - fmaxf(b4.y, wy1);
                iw = fmaxf(iw, 0.0f);
                ih = fmaxf(ih, 0.0f);
                float inter = iw * ih;
                bool s = (lane > i) && (lane < m) &&
                         (inter > NMS_TH * (ar + wa - inter + 1e-9f));
                removed |= __ballot_sync(FULL, s);
            }
            if (lane < m && ((keepB >> lane) & 1u) && ((pos >> 9) == half))
                keep[pos] = 1.0f;
        } else {
            // generic fallback (astronomically rare): select-min over merged list
            while (true) {
                unsigned long long bestk = ~0ull;
                for (int idx = lane; idx < ncand; idx += 32) {
                    if (sstate[idx] != 0u) continue;
                    unsigned long long k2 = skeyAll[idx];
                    if ((int)((k2 >> 42) & 0x7Fu) == c && k2 < bestk) bestk = k2;
                }
                #pragma unroll
                for (int d = 16; d >= 1; d >>= 1) {
                    unsigned long long o = __shfl_xor_sync(FULL, bestk, d);
                    if (o < bestk) bestk = o;
                }
                if (bestk == ~0ull) break;
                int wpos = (int)(bestk & 0x3FFu);
                int wli  = (int)posmap[wpos] & 1023;
                float4 wb = sboxAll[wli];
                float  wa = (wb.z - wb.x) * (wb.w - wb.y);
                if (lane == 0) {
                    sstate[wli] = 1u;
                    if ((wpos >> 9) == half) keep[wpos] = 1.0f;
                }
                __syncwarp(FULL);
                for (int idx = lane; idx < ncand; idx += 32) {
                    if (sstate[idx] != 0u) continue;
                    unsigned long long k2 = skeyAll[idx];
                    if ((int)((k2 >> 42) & 0x7Fu) != c) continue;
                    float4 b2 = sboxAll[idx];
                    float a2 = (b2.z - b2.x) * (b2.w - b2.y);
                    float iw = fminf(b2.z, wb.z) - fmaxf(b2.x, wb.x);
                    float ih = fminf(b2.w, wb.w) - fmaxf(b2.y, wb.y);
                    iw = fmaxf(iw, 0.0f);
                    ih = fmaxf(ih, 0.0f);
                    float inter = iw * ih;
                    if (inter > NMS_TH * (a2 + wa - inter + 1e-9f)) sstate[idx] = 2u;
                }
                __syncwarp(FULL);
            }
        }
    }
    __syncthreads();

    // ---------------- cleanup ticket: restore flag invariants ----------------
    if (t == 0) {
        unsigned r = atomicAdd(&g_done[n], 1u);
        if (r == 1u) { g_flag[n] = 0u; g_done[n] = 0u; }
    }
}

extern "C" void kernel_launch(void* const* d_in, const int* in_sizes, int n_in,
                              void* d_out, int out_size)
{
    const float* in = (const float*)d_in[0];
    float* out = (float*)d_out;
    cudaFuncSetAttribute(fastestdet_kernel,
                         cudaFuncAttributeMaxDynamicSharedMemorySize, SMEM_BYTES);
    fastestdet_kernel<<<N_IMG * 2, 1024, SMEM_BYTES>>>(in, out);
}

// round 14
// speedup vs baseline: 1.0862x; 1.0862x over previous
#include <cuda_runtime.h>
#include <math.h>

#define CONF_TH 0.25f
#define NMS_TH  0.35f
#define FULL    0xffffffffu

static constexpr int N_IMG = 64;
static constexpr int HW    = 1024;   // 32*32
static constexpr int NCH   = 85;
static constexpr int NCLS  = 80;
static constexpr int SLOTS = 32;
static constexpr int CTA_LINES = NCH * HW * 4 / 128;   // 2720 x 128B lines per image

// dynamic smem layout (bytes):
//  pval  float4[1024] @      0 (16384)   partial argmax values  [q*256+g]
//  pidx  int4  [1024] @  16384 (16384)   partial argmax indices
//  skey  u64   [1024] @  32768 ( 8192)   per-pixel key (fallback path)
//  sslot u64 [80*32]  @  40960 (20480)   per-class candidate slots
//  scnt  u32   [80]   @  61440 (  320)   per-class candidate count
//  keepS u32   [1024] @  61760 ( 4096)   keep flags
//  sbox  float4[1024] @  65856 (16384)   boxes by pixel
static constexpr int SMEM_BYTES = 82240;

__device__ __forceinline__ unsigned long long bitonic_shfl_step(
    unsigned long long key, int j, bool up, int t)
{
    unsigned long long p = __shfl_xor_sync(FULL, key, j);
    bool low     = ((t & j) == 0);
    bool takeMin = (low == up);
    bool swap    = takeMin ? (p < key) : (p > key);
    return swap ? p : key;
}

__global__ __launch_bounds__(1024, 1)
void fastestdet_kernel(const float* __restrict__ in, float* __restrict__ out)
{
    extern __shared__ unsigned char smem_raw[];
    float4*             pval  = (float4*)(smem_raw);
    int4*               pidx  = (int4*)  (smem_raw + 16384);
    unsigned long long* skey  = (unsigned long long*)(smem_raw + 32768);
    unsigned long long* sslot = (unsigned long long*)(smem_raw + 40960);
    unsigned*           scnt  = (unsigned*)(smem_raw + 61440);
    unsigned*           keepS = (unsigned*)(smem_raw + 61760);
    float4*             sbox  = (float4*)(smem_raw + 65856);

    const int n    = blockIdx.x;
    const int t    = threadIdx.x;
    const int lane = t & 31;
    const int wid  = t >> 5;
    const int g    = t & 255;    // pixel group (pixels 4g..4g+3)
    const int q    = t >> 8;     // channel chunk (20 classes each)

    // ---------------- L2 prefetch prologue: whole image into L2 ----------------
    // Fire-and-forget fills are not bound by the L1tex load-return window; L2
    // fills at chip DRAM bandwidth while demand LDGs below cycle at L2-hit RTT.
    {
        const char* gb = (const char*)(in + (size_t)n * NCH * HW);
        #pragma unroll
        for (int r = 0; r < 3; r++) {
            int line = t + r * 1024;
            if (line < CTA_LINES)
                asm volatile("prefetch.global.L2 [%0];" :: "l"(gb + (size_t)line * 128));
        }
    }

    keepS[t] = 0u;
    if (t < NCLS) scnt[t] = 0u;

    // ---------------- decode phase 1: partial argmax over 20 classes ----------------
    const float4* base = (const float4*)(in + (size_t)n * NCH * HW) + g;

    float4 bv = make_float4(-INFINITY, -INFINITY, -INFINITY, -INFINITY);
    int4   bj = make_int4(0, 0, 0, 0);
    const int c0 = q * 20;
    #pragma unroll
    for (int cc = 0; cc < 20; cc++) {
        int c = c0 + cc;
        float4 v = base[(5 + c) * 256];
        if (v.x > bv.x) { bv.x = v.x; bj.x = c; }
        if (v.y > bv.y) { bv.y = v.y; bj.y = c; }
        if (v.z > bv.z) { bv.z = v.z; bj.z = c; }
        if (v.w > bv.w) { bv.w = v.w; bj.w = c; }
    }
    pval[q * 256 + g] = bv;
    pidx[q * 256 + g] = bj;

    // chunk 0 also loads obj + regression channels (kept in registers across the barrier)
    float4 pobj, r0, r1, r2, r3;
    if (q == 0) {
        pobj = base[0 * 256];
        r0   = base[1 * 256];
        r1   = base[2 * 256];
        r2   = base[3 * 256];
        r3   = base[4 * 256];
    }
    __syncthreads();

    // ---------------- decode phase 2: merge + box math (chunk-0 threads) ----------------
    if (q == 0) {
        float4 mv = pval[g];
        int4   mj = pidx[g];
        #pragma unroll
        for (int qq = 1; qq < 4; qq++) {
            float4 v = pval[qq * 256 + g];
            int4   j = pidx[qq * 256 + g];
            if (v.x > mv.x) { mv.x = v.x; mj.x = j.x; }   // strict >: lower chunk wins ties
            if (v.y > mv.y) { mv.y = v.y; mj.y = j.y; }
            if (v.z > mv.z) { mv.z = v.z; mj.z = j.z; }
            if (v.w > mv.w) { mv.w = v.w; mj.w = j.w; }
        }

        float sc[4]  = { pobj.x * mv.x, pobj.y * mv.y, pobj.z * mv.z, pobj.w * mv.w };
        float rr0[4] = { r0.x, r0.y, r0.z, r0.w };
        float rr1[4] = { r1.x, r1.y, r1.z, r1.w };
        float rr2[4] = { r2.x, r2.y, r2.z, r2.w };
        float rr3[4] = { r3.x, r3.y, r3.z, r3.w };
        int   cl[4]  = { mj.x, mj.y, mj.z, mj.w };

        float vals[24];
        #pragma unroll
        for (int l = 0; l < 4; l++) {
            int p = g * 4 + l;
            float gx = (float)(p & 31);
            float gy = (float)(p >> 5);
            float bcx = (tanhf(rr0[l]) + gx) * (1.0f / 32.0f);
            float bcy = (tanhf(rr1[l]) + gy) * (1.0f / 32.0f);
            float bw  = 1.0f / (1.0f + expf(-rr2[l]));
            float bh  = 1.0f / (1.0f + expf(-rr3[l]));
            float x1 = bcx - 0.5f * bw;
            float y1 = bcy - 0.5f * bh;
            float x2 = bcx + 0.5f * bw;
            float y2 = bcy + 0.5f * bh;

            vals[l * 6 + 0] = x1; vals[l * 6 + 1] = y1;
            vals[l * 6 + 2] = x2; vals[l * 6 + 3] = y2;
            vals[l * 6 + 4] = sc[l]; vals[l * 6 + 5] = (float)cl[l];

            sbox[p] = make_float4(x1, y1, x2, y2);

            bool cand = sc[l] > CONF_TH;
            unsigned u = __float_as_uint(sc[l]);
            u = (u & 0x80000000u) ? ~u : (u | 0x80000000u);   // ascending-sortable
            unsigned long long key = cand
                ? (((unsigned long long)(unsigned)cl[l] << 42)
                   | ((unsigned long long)(~u) << 10)
                   | (unsigned)p)
                : (0x8000000000000000ull | (unsigned)p);
            skey[p] = key;
            if (cand) {
                unsigned slot = atomicAdd(&scnt[cl[l]], 1u);
                if (slot < SLOTS) sslot[cl[l] * SLOTS + slot] = key;
            }
        }

        // boxes+score+cls out: 24 contiguous floats = 6 float4 stores
        float4* ob4 = (float4*)(out + ((size_t)n * HW + g * 4) * 6);
        #pragma unroll
        for (int qq = 0; qq < 6; qq++)
            ob4[qq] = make_float4(vals[qq * 4 + 0], vals[qq * 4 + 1],
                                  vals[qq * 4 + 2], vals[qq * 4 + 3]);
    }
    __syncthreads();

    // ---------------- warp-per-class greedy NMS (smem, no barriers) ----------------
    for (int c = wid; c < NCLS; c += 32) {
        int m = (int)scnt[c];
        if (m == 0) continue;

        if (m <= SLOTS) {
            // fast path: sort ≤32 keys in registers, ballot-greedy
            unsigned long long kk = (lane < m) ? sslot[c * SLOTS + lane] : ~0ull;
            #pragma unroll
            for (int k = 2; k <= 32; k <<= 1) {
                #pragma unroll
                for (int j = k >> 1; j >= 1; j >>= 1)
                    kk = bitonic_shfl_step(kk, j, (lane & k) == 0, lane);
            }
            int pos = (int)(kk & 0x3FFu);
            float4 b4 = sbox[pos];                 // lane>=m: pos=1023, in-bounds, unused
            float  ar = (b4.z - b4.x) * (b4.w - b4.y);

            unsigned removed = 0u, keepB = 0u;
            for (int i = 0; i < m; i++) {
                if ((removed >> i) & 1u) continue; // uniform across warp
                keepB |= 1u << i;
                float wx1 = __shfl_sync(FULL, b4.x, i);
                float wy1 = __shfl_sync(FULL, b4.y, i);
                float wx2 = __shfl_sync(FULL, b4.z, i);
                float wy2 = __shfl_sync(FULL, b4.w, i);
                float wa  = __shfl_sync(FULL, ar,   i);
                float iw = fminf(b4.z, wx2) - fmaxf(b4.x, wx1);
                float ih = fminf(b4.w, wy2) - fmaxf(b4.y, wy1);
                iw = fmaxf(iw, 0.0f);
                ih = fmaxf(ih, 0.0f);
                float inter = iw * ih;
                bool s = (lane > i) && (lane < m) &&
                         (inter > NMS_TH * (ar + wa - inter + 1e-9f));
                removed |= __ballot_sync(FULL, s);
            }
            if (lane < m && ((keepB >> lane) & 1u)) keepS[pos] = 1u;
        } else {
            // generic fallback (astronomically rare): scan all pixel keys
            unsigned alive = 0u;            // lane owns pixels k*32+lane
            for (int k = 0; k < 32; k++) {
                unsigned long long key = skey[k * 32 + lane];
                bool elig = ((key >> 63) == 0ull) && ((int)((key >> 42) & 0x7Fu) == c);
                if (elig) alive |= 1u << k;
            }
            while (true) {
                unsigned long long bestk = ~0ull;
                for (int k = 0; k < 32; k++)
                    if ((alive >> k) & 1u) {
                        unsigned long long key = skey[k * 32 + lane];
                        if (key < bestk) bestk = key;
                    }
                #pragma unroll
                for (int d = 16; d >= 1; d >>= 1) {
                    unsigned long long o = __shfl_xor_sync(FULL, bestk, d);
                    if (o < bestk) bestk = o;
                }
                if (bestk == ~0ull) break;
                int wpos = (int)(bestk & 0x3FFu);
                float4 wb = sbox[wpos];
                float  wa = (wb.z - wb.x) * (wb.w - wb.y);
                if (lane == (wpos & 31)) {
                    alive &= ~(1u << (wpos >> 5));
                    keepS[wpos] = 1u;
                }
                for (int k = 0; k < 32; k++)
                    if ((alive >> k) & 1u) {
                        int p2 = k * 32 + lane;
                        float4 b2 = sbox[p2];
                        float a2 = (b2.z - b2.x) * (b2.w - b2.y);
                        float iw = fminf(b2.z, wb.z) - fmaxf(b2.x, wb.x);
                        float ih = fminf(b2.w, wb.w) - fmaxf(b2.y, wb.y);
                        iw = fmaxf(iw, 0.0f);
                        ih = fmaxf(ih, 0.0f);
                        float inter = iw * ih;
                        if (inter > NMS_TH * (a2 + wa - inter + 1e-9f))
                            alive &= ~(1u << k);
                    }
                __syncwarp(FULL);
            }
        }
    }
    __syncthreads();

    // ---------------- keep output (original order) ----------------
    out[(size_t)N_IMG * HW * 6 + (size_t)n * HW + t] = (float)keepS[t];
}

extern "C" void kernel_launch(void* const* d_in, const int* in_sizes, int n_in,
                              void* d_out, int out_size)
{
    const float* in = (const float*)d_in[0];
    float* out = (float*)d_out;
    cudaFuncSetAttribute(fastestdet_kernel,
                         cudaFuncAttributeMaxDynamicSharedMemorySize, SMEM_BYTES);
    fastestdet_kernel<<<N_IMG, 1024, SMEM_BYTES>>>(in, out);
}

// round 15
// speedup vs baseline: 1.0943x; 1.0074x over previous
#include <cuda_runtime.h>
#include <math.h>

#define CONF_TH 0.25f
#define NMS_TH  0.35f
#define FULL    0xffffffffu

static constexpr int N_IMG = 64;
static constexpr int HW    = 1024;   // 32*32
static constexpr int NCH   = 85;
static constexpr int NCLS  = 80;
static constexpr int SLOTS = 32;
static constexpr int CTA_LINES = NCH * HW * 4 / 128;   // 2720 x 128B lines per image

// dynamic smem layout (bytes):
//  pval  float4[1024] @      0 (16384)   partial argmax values  [q*256+g]
//  pidx  int4  [1024] @  16384 (16384)   partial argmax indices
//  skey  u64   [1024] @  32768 ( 8192)   per-pixel key (fallback path)
//  sslot u64 [80*32]  @  40960 (20480)   per-class candidate slots
//  scnt  u32   [80]   @  61440 (  320)   per-class candidate count
//  keepS u32   [1024] @  61760 ( 4096)   keep flags
//  sbox  float4[1024] @  65856 (16384)   boxes by pixel
static constexpr int SMEM_BYTES = 82240;

__device__ __forceinline__ unsigned long long bitonic_shfl_step(
    unsigned long long key, int j, bool up, int t)
{
    unsigned long long p = __shfl_xor_sync(FULL, key, j);
    bool low     = ((t & j) == 0);
    bool takeMin = (low == up);
    bool swap    = takeMin ? (p < key) : (p > key);
    return swap ? p : key;
}

__global__ __launch_bounds__(1024, 1)
void fastestdet_kernel(const float* __restrict__ in, float* __restrict__ out)
{
    extern __shared__ unsigned char smem_raw[];
    float4*             pval  = (float4*)(smem_raw);
    int4*               pidx  = (int4*)  (smem_raw + 16384);
    unsigned long long* skey  = (unsigned long long*)(smem_raw + 32768);
    unsigned long long* sslot = (unsigned long long*)(smem_raw + 40960);
    unsigned*           scnt  = (unsigned*)(smem_raw + 61440);
    unsigned*           keepS = (unsigned*)(smem_raw + 61760);
    float4*             sbox  = (float4*)(smem_raw + 65856);

    const int n    = blockIdx.x >> 1;   // image
    const int t    = threadIdx.x;

    // ================= odd CTAs: L2 warmer for image n, then exit =================
    if (blockIdx.x & 1) {
        const float* gb = in + (size_t)n * NCH * HW;
        float s = 0.0f;
        #pragma unroll
        for (int r = 0; r < 3; r++) {
            int line = t + r * 1024;
            if (line < CTA_LINES)
                s += __ldg(gb + (size_t)(CTA_LINES - 1 - line) * 32);   // 1 float per 128B line
        }
        ((volatile float*)smem_raw)[t] = s;   // DCE sink (smem store, never read)
        return;
    }

    // ================= even CTAs: exact R7 worker =================
    const int lane = t & 31;
    const int wid  = t >> 5;
    const int g    = t & 255;    // pixel group (pixels 4g..4g+3)
    const int q    = t >> 8;     // channel chunk (20 classes each)

    keepS[t] = 0u;
    if (t < NCLS) scnt[t] = 0u;

    // ---------------- decode phase 1: partial argmax over 20 classes ----------------
    const float4* base = (const float4*)(in + (size_t)n * NCH * HW) + g;

    float4 bv = make_float4(-INFINITY, -INFINITY, -INFINITY, -INFINITY);
    int4   bj = make_int4(0, 0, 0, 0);
    const int c0 = q * 20;
    #pragma unroll
    for (int cc = 0; cc < 20; cc++) {
        int c = c0 + cc;
        float4 v = base[(5 + c) * 256];
        if (v.x > bv.x) { bv.x = v.x; bj.x = c; }
        if (v.y > bv.y) { bv.y = v.y; bj.y = c; }
        if (v.z > bv.z) { bv.z = v.z; bj.z = c; }
        if (v.w > bv.w) { bv.w = v.w; bj.w = c; }
    }
    pval[q * 256 + g] = bv;
    pidx[q * 256 + g] = bj;

    // chunk 0 also loads obj + regression channels (kept in registers across the barrier)
    float4 pobj, r0, r1, r2, r3;
    if (q == 0) {
        pobj = base[0 * 256];
        r0   = base[1 * 256];
        r1   = base[2 * 256];
        r2   = base[3 * 256];
        r3   = base[4 * 256];
    }
    __syncthreads();

    // ---------------- decode phase 2: merge + box math (chunk-0 threads) ----------------
    if (q == 0) {
        float4 mv = pval[g];
        int4   mj = pidx[g];
        #pragma unroll
        for (int qq = 1; qq < 4; qq++) {
            float4 v = pval[qq * 256 + g];
            int4   j = pidx[qq * 256 + g];
            if (v.x > mv.x) { mv.x = v.x; mj.x = j.x; }   // strict >: lower chunk wins ties
            if (v.y > mv.y) { mv.y = v.y; mj.y = j.y; }
            if (v.z > mv.z) { mv.z = v.z; mj.z = j.z; }
            if (v.w > mv.w) { mv.w = v.w; mj.w = j.w; }
        }

        float sc[4]  = { pobj.x * mv.x, pobj.y * mv.y, pobj.z * mv.z, pobj.w * mv.w };
        float rr0[4] = { r0.x, r0.y, r0.z, r0.w };
        float rr1[4] = { r1.x, r1.y, r1.z, r1.w };
        float rr2[4] = { r2.x, r2.y, r2.z, r2.w };
        float rr3[4] = { r3.x, r3.y, r3.z, r3.w };
        int   cl[4]  = { mj.x, mj.y, mj.z, mj.w };

        float vals[24];
        #pragma unroll
        for (int l = 0; l < 4; l++) {
            int p = g * 4 + l;
            float gx = (float)(p & 31);
            float gy = (float)(p >> 5);
            float bcx = (tanhf(rr0[l]) + gx) * (1.0f / 32.0f);
            float bcy = (tanhf(rr1[l]) + gy) * (1.0f / 32.0f);
            float bw  = 1.0f / (1.0f + expf(-rr2[l]));
            float bh  = 1.0f / (1.0f + expf(-rr3[l]));
            float x1 = bcx - 0.5f * bw;
            float y1 = bcy - 0.5f * bh;
            float x2 = bcx + 0.5f * bw;
            float y2 = bcy + 0.5f * bh;

            vals[l * 6 + 0] = x1; vals[l * 6 + 1] = y1;
            vals[l * 6 + 2] = x2; vals[l * 6 + 3] = y2;
            vals[l * 6 + 4] = sc[l]; vals[l * 6 + 5] = (float)cl[l];

            sbox[p] = make_float4(x1, y1, x2, y2);

            bool cand = sc[l] > CONF_TH;
            unsigned u = __float_as_uint(sc[l]);
            u = (u & 0x80000000u) ? ~u : (u | 0x80000000u);   // ascending-sortable
            unsigned long long key = cand
                ? (((unsigned long long)(unsigned)cl[l] << 42)
                   | ((unsigned long long)(~u) << 10)
                   | (unsigned)p)
                : (0x8000000000000000ull | (unsigned)p);
            skey[p] = key;
            if (cand) {
                unsigned slot = atomicAdd(&scnt[cl[l]], 1u);
                if (slot < SLOTS) sslot[cl[l] * SLOTS + slot] = key;
            }
        }

        // boxes+score+cls out: 24 contiguous floats = 6 float4 stores
        float4* ob4 = (float4*)(out + ((size_t)n * HW + g * 4) * 6);
        #pragma unroll
        for (int qq = 0; qq < 6; qq++)
            ob4[qq] = make_float4(vals[qq * 4 + 0], vals[qq * 4 + 1],
                                  vals[qq * 4 + 2], vals[qq * 4 + 3]);
    }
    __syncthreads();

    // ---------------- warp-per-class greedy NMS (smem, no barriers) ----------------
    for (int c = wid; c < NCLS; c += 32) {
        int m = (int)scnt[c];
        if (m == 0) continue;

        if (m <= SLOTS) {
            // fast path: sort ≤32 keys in registers, ballot-greedy
            unsigned long long kk = (lane < m) ? sslot[c * SLOTS + lane] : ~0ull;
            #pragma unroll
            for (int k = 2; k <= 32; k <<= 1) {
                #pragma unroll
                for (int j = k >> 1; j >= 1; j >>= 1)
                    kk = bitonic_shfl_step(kk, j, (lane & k) == 0, lane);
            }
            int pos = (int)(kk & 0x3FFu);
            float4 b4 = sbox[pos];                 // lane>=m: pos=1023, in-bounds, unused
            float  ar = (b4.z - b4.x) * (b4.w - b4.y);

            unsigned removed = 0u, keepB = 0u;
            for (int i = 0; i < m; i++) {
                if ((removed >> i) & 1u) continue; // uniform across warp
                keepB |= 1u << i;
                float wx1 = __shfl_sync(FULL, b4.x, i);
                float wy1 = __shfl_sync(FULL, b4.y, i);
                float wx2 = __shfl_sync(FULL, b4.z, i);
                float wy2 = __shfl_sync(FULL, b4.w, i);
                float wa  = __shfl_sync(FULL, ar,   i);
                float iw = fminf(b4.z, wx2) - fmaxf(b4.x, wx1);
                float ih = fminf(b4.w, wy2) - fmaxf(b4.y, wy1);
                iw = fmaxf(iw, 0.0f);
                ih = fmaxf(ih, 0.0f);
                float inter = iw * ih;
                bool s = (lane > i) && (lane < m) &&
                         (inter > NMS_TH * (ar + wa - inter + 1e-9f));
                removed |= __ballot_sync(FULL, s);
            }
            if (lane < m && ((keepB >> lane) & 1u)) keepS[pos] = 1u;
        } else {
            // generic fallback (astronomically rare): scan all pixel keys
            unsigned alive = 0u;            // lane owns pixels k*32+lane
            for (int k = 0; k < 32; k++) {
                unsigned long long key = skey[k * 32 + lane];
                bool elig = ((key >> 63) == 0ull) && ((int)((key >> 42) & 0x7Fu) == c);
                if (elig) alive |= 1u << k;
            }
            while (true) {
                unsigned long long bestk = ~0ull;
                for (int k = 0; k < 32; k++)
                    if ((alive >> k) & 1u) {
                        unsigned long long key = skey[k * 32 + lane];
                        if (key < bestk) bestk = key;
                    }
                #pragma unroll
                for (int d = 16; d >= 1; d >>= 1) {
                    unsigned long long o = __shfl_xor_sync(FULL, bestk, d);
                    if (o < bestk) bestk = o;
                }
                if (bestk == ~0ull) break;
                int wpos = (int)(bestk & 0x3FFu);
                float4 wb = sbox[wpos];
                float  wa = (wb.z - wb.x) * (wb.w - wb.y);
                if (lane == (wpos & 31)) {
                    alive &= ~(1u << (wpos >> 5));
                    keepS[wpos] = 1u;
                }
                for (int k = 0; k < 32; k++)
                    if ((alive >> k) & 1u) {
                        int p2 = k * 32 + lane;
                        float4 b2 = sbox[p2];
                        float a2 = (b2.z - b2.x) * (b2.w - b2.y);
                        float iw = fminf(b2.z, wb.z) - fmaxf(b2.x, wb.x);
                        float ih = fminf(b2.w, wb.w) - fmaxf(b2.y, wb.y);
                        iw = fmaxf(iw, 0.0f);
                        ih = fmaxf(ih, 0.0f);
                        float inter = iw * ih;
                        if (inter > NMS_TH * (a2 + wa - inter + 1e-9f))
                            alive &= ~(1u << k);
                    }
                __syncwarp(FULL);
            }
        }
    }
    __syncthreads();

    // ---------------- keep output (original order) ----------------
    out[(size_t)N_IMG * HW * 6 + (size_t)n * HW + t] = (float)keepS[t];
}

extern "C" void kernel_launch(void* const* d_in, const int* in_sizes, int n_in,
                              void* d_out, int out_size)
{
    const float* in = (const float*)d_in[0];
    float* out = (float*)d_out;
    cudaFuncSetAttribute(fastestdet_kernel,
                         cudaFuncAttributeMaxDynamicSharedMemorySize, SMEM_BYTES);
    fastestdet_kernel<<<N_IMG * 2, 1024, SMEM_BYTES>>>(in, out);
}

// round 16
// speedup vs baseline: 1.1065x; 1.0112x over previous
#include <cuda_runtime.h>
#include <math.h>
#include <stdint.h>

#define CONF_TH 0.25f
#define NMS_TH  0.35f
#define FULL    0xffffffffu

static constexpr int N_IMG = 64;
static constexpr int HW    = 1024;   // 32*32
static constexpr int NCH   = 85;
static constexpr int NCLS  = 80;
static constexpr int SLOTS = 32;

static constexpr int C0_BYTES  = 5 * HW * 4;      // 20480 (obj + 4 reg channels)
static constexpr int CCH       = 10;              // classes per class-chunk
static constexpr int CBYTES    = CCH * HW * 4;    // 40960
static constexpr int NCHUNK    = 9;               // 1 + 8
static constexpr int RING      = 4;
static constexpr int SLOT_FLT  = CCH * HW;        // 10240 floats per slot

// dynamic smem layout (bytes):
//  ring   float[4*10240] @      0 (163840)
//  sbox   float4[1024]   @ 163840 ( 16384)
//  sslot  u64[80*32]     @ 180224 ( 20480)
//  skey   u64[1024]      @ 200704 (  8192)
//  keepS  u32[1024]      @ 208896 (  4096)
//  scnt   u32[80]        @ 212992 (   320)
//  mbar   u64[4]         @ 213312 (    32)
static constexpr int SMEM_BYTES = 213344;

__device__ __forceinline__ void mbar_init(unsigned mb, unsigned cnt) {
    asm volatile("mbarrier.init.shared.b64 [%0], %1;" :: "r"(mb), "r"(cnt) : "memory");
}

__device__ __forceinline__ void issue_chunk(const void* src, unsigned dst, unsigned mb,
                                            unsigned bytes) {
    asm volatile("mbarrier.arrive.expect_tx.shared.b64 _, [%0], %1;"
                 :: "r"(mb), "r"(bytes) : "memory");
    asm volatile("cp.async.bulk.shared::cluster.global.mbarrier::complete_tx::bytes "
                 "[%0], [%1], %2, [%3];"
                 :: "r"(dst), "l"(src), "r"(bytes), "r"(mb) : "memory");
}

__device__ __forceinline__ void wait_parity(unsigned mb, unsigned ph) {
    asm volatile(
        "{\n\t.reg .pred P1;\n\t"
        "WAITL_%=:\n\t"
        "mbarrier.try_wait.parity.acquire.cta.shared::cta.b64 P1, [%0], %1, 0x989680;\n\t"
        "@P1 bra.uni WDONE_%=;\n\t"
        "bra.uni WAITL_%=;\n\t"
        "WDONE_%=:\n\t}"
        :: "r"(mb), "r"(ph) : "memory");
}

__device__ __forceinline__ unsigned long long bitonic_shfl_step(
    unsigned long long key, int j, bool up, int t)
{
    unsigned long long p = __shfl_xor_sync(FULL, key, j);
    bool low     = ((t & j) == 0);
    bool takeMin = (low == up);
    bool swap    = takeMin ? (p < key) : (p > key);
    return swap ? p : key;
}

// right operand wins only on strict > : preserves first-occurrence (lower index) ties
__device__ __forceinline__ void amax2(float vl, int il, float vr, int ir,
                                      float& vo, int& io)
{
    bool g = vr > vl;
    vo = g ? vr : vl;
    io = g ? ir : il;
}

__global__ __launch_bounds__(1024, 1)
void fastestdet_kernel(const float* __restrict__ in, float* __restrict__ out)
{
    extern __shared__ unsigned char smem_raw[];
    float*              ringf = (float*)(smem_raw);
    float4*             sbox  = (float4*)(smem_raw + 163840);
    unsigned long long* sslot = (unsigned long long*)(smem_raw + 180224);
    unsigned long long* skey  = (unsigned long long*)(smem_raw + 200704);
    unsigned*           keepS = (unsigned*)(smem_raw + 208896);
    unsigned*           scnt  = (unsigned*)(smem_raw + 212992);

    const unsigned ring_u32 = (unsigned)__cvta_generic_to_shared(smem_raw);
    const unsigned mbar_u32 = ring_u32 + 213312;

    const int n    = blockIdx.x;
    const int t    = threadIdx.x;
    const int lane = t & 31;
    const int wid  = t >> 5;

    keepS[t] = 0u;
    if (t < NCLS) scnt[t] = 0u;

    const char* gbase = (const char*)(in + (size_t)n * NCH * HW);

    if (t == 0) {
        #pragma unroll
        for (int s = 0; s < RING; s++) mbar_init(mbar_u32 + s * 8, 1u);
        asm volatile("fence.proxy.async.shared::cta;" ::: "memory");
    }
    __syncthreads();

    // prologue: chunk 0 (20KB) into slot 0, chunks 1..3 (40KB) into slots 1..3
    if (t == 0) {
        issue_chunk(gbase, ring_u32, mbar_u32, (unsigned)C0_BYTES);
        #pragma unroll
        for (int j = 1; j < RING; j++)
            issue_chunk(gbase + C0_BYTES + (size_t)(j - 1) * CBYTES,
                        ring_u32 + (unsigned)j * CBYTES,
                        mbar_u32 + (unsigned)j * 8,
                        (unsigned)CBYTES);
    }

    // ---------------- decode: TMA ring consume, tournament argmax ----------------
    float pobj = 0.f, r0 = 0.f, r1 = 0.f, r2 = 0.f, r3 = 0.f;
    float best = -INFINITY;
    int   bi   = 0;

    for (int k = 0; k < NCHUNK; k++) {
        const int s = k & 3;
        wait_parity(mbar_u32 + s * 8, (unsigned)((k >> 2) & 1));

        const float* cf = ringf + s * SLOT_FLT;
        if (k == 0) {
            pobj = cf[0 * HW + t];
            r0   = cf[1 * HW + t];
            r1   = cf[2 * HW + t];
            r2   = cf[3 * HW + t];
            r3   = cf[4 * HW + t];
        } else {
            const int c0 = (k - 1) * CCH;
            float v0 = cf[0 * HW + t], v1 = cf[1 * HW + t];
            float v2 = cf[2 * HW + t], v3 = cf[3 * HW + t];
            float v4 = cf[4 * HW + t], v5 = cf[5 * HW + t];
            float v6 = cf[6 * HW + t], v7 = cf[7 * HW + t];
            float v8 = cf[8 * HW + t], v9 = cf[9 * HW + t];
            // tournament (ILP), left operand always the lower index block
            float a0v, a1v, a2v, a3v, a4v; int a0i, a1i, a2i, a3i, a4i;
            amax2(v0, c0 + 0, v1, c0 + 1, a0v, a0i);
            amax2(v2, c0 + 2, v3, c0 + 3, a1v, a1i);
            amax2(v4, c0 + 4, v5, c0 + 5, a2v, a2i);
            amax2(v6, c0 + 6, v7, c0 + 7, a3v, a3i);
            amax2(v8, c0 + 8, v9, c0 + 9, a4v, a4i);
            float b0v, b1v; int b0i, b1i;
            amax2(a0v, a0i, a1v, a1i, b0v, b0i);
            amax2(a2v, a2i, a3v, a3i, b1v, b1i);
            float d0v; int d0i;
            amax2(b0v, b0i, b1v, b1i, d0v, d0i);
            float ev; int ei;
            amax2(d0v, d0i, a4v, a4i, ev, ei);
            if (ev > best) { best = ev; bi = ei; }   // strict >: earlier chunk wins ties
        }

        if (k <= 4) {                    // slot s will be refilled with chunk k+4
            __syncthreads();
            if (t == 0)
                issue_chunk(gbase + C0_BYTES + (size_t)(k + 3) * CBYTES,
                            ring_u32 + (unsigned)s * CBYTES,
                            mbar_u32 + (unsigned)s * 8,
                            (unsigned)CBYTES);
        }
    }

    // ---------------- box math + outputs + candidate scatter ----------------
    {
        float score = pobj * best;
        float gx = (float)(t & 31);
        float gy = (float)(t >> 5);
        float bcx = (tanhf(r0) + gx) * (1.0f / 32.0f);
        float bcy = (tanhf(r1) + gy) * (1.0f / 32.0f);
        float bw  = 1.0f / (1.0f + expf(-r2));
        float bh  = 1.0f / (1.0f + expf(-r3));
        float x1 = bcx - 0.5f * bw;
        float y1 = bcy - 0.5f * bh;
        float x2 = bcx + 0.5f * bw;
        float y2 = bcy + 0.5f * bh;

        float* ob = out + ((size_t)n * HW + t) * 6;
        ob[0] = x1; ob[1] = y1; ob[2] = x2; ob[3] = y2;
        ob[4] = score; ob[5] = (float)bi;

        sbox[t] = make_float4(x1, y1, x2, y2);

        bool cand = score > CONF_TH;
        unsigned u = __float_as_uint(score);
        u = (u & 0x80000000u) ? ~u : (u | 0x80000000u);   // ascending-sortable
        unsigned long long key = cand
            ? (((unsigned long long)(unsigned)bi << 42)
               | ((unsigned long long)(~u) << 10)
               | (unsigned)t)
            : (0x8000000000000000ull | (unsigned)t);
        skey[t] = key;
        if (cand) {
            unsigned slot = atomicAdd(&scnt[bi], 1u);
            if (slot < SLOTS) sslot[bi * SLOTS + slot] = key;
        }
    }
    __syncthreads();

    // ---------------- warp-per-class greedy NMS (smem, no barriers) ----------------
    for (int c = wid; c < NCLS; c += 32) {
        int m = (int)scnt[c];
        if (m == 0) continue;

        if (m <= SLOTS) {
            // fast path: sort ≤32 keys in registers, ballot-greedy
            unsigned long long kk = (lane < m) ? sslot[c * SLOTS + lane] : ~0ull;
            #pragma unroll
            for (int k = 2; k <= 32; k <<= 1) {
                #pragma unroll
                for (int j = k >> 1; j >= 1; j >>= 1)
                    kk = bitonic_shfl_step(kk, j, (lane & k) == 0, lane);
            }
            int pos = (int)(kk & 0x3FFu);
            float4 b4 = sbox[pos];                 // lane>=m: pos=1023, in-bounds, unused
            float  ar = (b4.z - b4.x) * (b4.w - b4.y);

            unsigned removed = 0u, keepB = 0u;
            for (int i = 0; i < m; i++) {
                if ((removed >> i) & 1u) continue; // uniform across warp
                keepB |= 1u << i;
                float wx1 = __shfl_sync(FULL, b4.x, i);
                float wy1 = __shfl_sync(FULL, b4.y, i);
                float wx2 = __shfl_sync(FULL, b4.z, i);
                float wy2 = __shfl_sync(FULL, b4.w, i);
                float wa  = __shfl_sync(FULL, ar,   i);
                float iw = fminf(b4.z, wx2) - fmaxf(b4.x, wx1);
                float ih = fminf(b4.w, wy2) - fmaxf(b4.y, wy1);
                iw = fmaxf(iw, 0.0f);
                ih = fmaxf(ih, 0.0f);
                float inter = iw * ih;
                bool s = (lane > i) && (lane < m) &&
                         (inter > NMS_TH * (ar + wa - inter + 1e-9f));
                removed |= __ballot_sync(FULL, s);
            }
            if (lane < m && ((keepB >> lane) & 1u)) keepS[pos] = 1u;
        } else {
            // generic fallback (astronomically rare): scan all pixel keys
            unsigned alive = 0u;            // lane owns pixels k*32+lane
            for (int k = 0; k < 32; k++) {
                unsigned long long key = skey[k * 32 + lane];
                bool elig = ((key >> 63) == 0ull) && ((int)((key >> 42) & 0x7Fu) == c);
                if (elig) alive |= 1u << k;
            }
            while (true) {
                unsigned long long bestk = ~0ull;
                for (int k = 0; k < 32; k++)
                    if ((alive >> k) & 1u) {
                        unsigned long long key = skey[k * 32 + lane];
                        if (key < bestk) bestk = key;
                    }
                #pragma unroll
                for (int d = 16; d >= 1; d >>= 1) {
                    unsigned long long o = __shfl_xor_sync(FULL, bestk, d);
                    if (o < bestk) bestk = o;
                }
                if (bestk == ~0ull) break;
                int wpos = (int)(bestk & 0x3FFu);
                float4 wb = sbox[wpos];
                float  wa = (wb.z - wb.x) * (wb.w - wb.y);
                if (lane == (wpos & 31)) {
                    alive &= ~(1u << (wpos >> 5));
                    keepS[wpos] = 1u;
                }
                for (int k = 0; k < 32; k++)
                    if ((alive >> k) & 1u) {
                        int p2 = k * 32 + lane;
                        float4 b2 = sbox[p2];
                        float a2 = (b2.z - b2.x) * (b2.w - b2.y);
                        float iw = fminf(b2.z, wb.z) - fmaxf(b2.x, wb.x);
                        float ih = fminf(b2.w, wb.w) - fmaxf(b2.y, wb.y);
                        iw = fmaxf(iw, 0.0f);
                        ih = fmaxf(ih, 0.0f);
                        float inter = iw * ih;
                        if (inter > NMS_TH * (a2 + wa - inter + 1e-9f))
                            alive &= ~(1u << k);
                    }
                __syncwarp(FULL);
            }
        }
    }
    __syncthreads();

    // ---------------- keep output (original order) ----------------
    out[(size_t)N_IMG * HW * 6 + (size_t)n * HW + t] = (float)keepS[t];
}

extern "C" void kernel_launch(void* const* d_in, const int* in_sizes, int n_in,
                              void* d_out, int out_size)
{
    const float* in = (const float*)d_in[0];
    float* out = (float*)d_out;
    cudaFuncSetAttribute(fastestdet_kernel,
                         cudaFuncAttributeMaxDynamicSharedMemorySize, SMEM_BYTES);
    fastestdet_kernel<<<N_IMG, 1024, SMEM_BYTES>>>(in, out);
}